// round 13
// baseline (speedup 1.0000x reference)
#include <cuda_runtime.h>
#include <cuda_bf16.h>
#include <cstdint>

// ---------------- problem constants ----------------
static constexpr int N_  = 16;
static constexpr int C_  = 256;
static constexpr int H_  = 56;
static constexpr int W_  = 56;
static constexpr int K_  = 256;
static constexpr int HW  = H_ * W_;          // 3136
static constexpr int CHW = C_ * HW;          // 802816
static constexpr long long NE_X = (long long)N_ * CHW;   // 12,845,056
static constexpr int NE_W = K_ * C_ * 9;     // 589,824
static constexpr int NG_W = NE_W / 36;       // 16,384
static constexpr int MGEMM = N_ * HW;        // 50,176 = 392*128

// ---------------- device scratch ----------------
__device__ __nv_bfloat16 g_xq_nchw[12845056];
__device__ __nv_bfloat16 g_xq[12845056];        // NHWC
__device__ __nv_bfloat16 g_wt[9 * 256 * 256];   // [rs][kout][c]

// ---------------- BFP quantization ----------------
__device__ __forceinline__ float bfp_apply(float v, float inv, float scale) {
    float r = rintf(v * inv);                 // round-half-even == jnp.round
    r = fminf(fmaxf(r, -128.0f), 127.0f);
    return r * scale;
}

// ---------------- fused quantize: x blocks + w blocks in one launch ----------
static constexpr int QX_GROUPS = 256;
static constexpr int QX_ELEMS  = QX_GROUPS * 36;          // 9216
static constexpr long long NE_X4 = NE_X / 4;              // float4 count (exact)
static constexpr int NBX = (int)((NE_X + QX_ELEMS - 1) / QX_ELEMS);   // 1394
static constexpr int NBW = NG_W / 8;                      // 2048

__device__ __forceinline__ void store_w(int f, float q) {
    int kout = f / 2304;
    int rem  = f - kout * 2304;
    int c    = rem / 9;
    int rs   = rem - c * 9;
    g_wt[(rs * K_ + kout) * C_ + c] = __float2bfloat16(q);
}

__global__ void __launch_bounds__(256)
quant_kernel(const float* __restrict__ x, const float* __restrict__ w) {
    const int tid = threadIdx.x;
    if (blockIdx.x < (unsigned)NBX) {
        __shared__ float s[QX_ELEMS];                     // 36 KB
        const long long b4 = (long long)blockIdx.x * (QX_ELEMS / 4);

        const float4* x4 = (const float4*)x;
        float4* s4 = (float4*)s;
        #pragma unroll
        for (int k = 0; k < 9; ++k) {
            long long f = b4 + tid + k * 256;
            float4 v = (f < NE_X4) ? x4[f] : make_float4(0.f, 0.f, 0.f, 0.f);
            s4[tid + k * 256] = v;
        }
        __syncthreads();

        float4 v[9];
        const float4* sg4 = (const float4*)s + tid * 9;
        #pragma unroll
        for (int j = 0; j < 9; ++j) v[j] = sg4[j];

        float m = 0.0f;
        #pragma unroll
        for (int j = 0; j < 9; ++j)
            m = fmaxf(m, fmaxf(fmaxf(fabsf(v[j].x), fabsf(v[j].y)),
                               fmaxf(fabsf(v[j].z), fabsf(v[j].w))));
        float scale = 0.0f, inv = 0.0f;
        if (m > 0.0f) {
            int e;
            frexpf(m, &e);
            scale = ldexpf(1.0f, e - 8);
            inv   = ldexpf(1.0f, 8 - e);
        }
        __syncthreads();     // all reads done before in-place overwrite

        uint32_t* qg = (uint32_t*)s + tid * 18;
        if (m > 0.0f) {
            #pragma unroll
            for (int j = 0; j < 9; ++j) {
                float a0 = bfp_apply(v[j].x, inv, scale);
                float a1 = bfp_apply(v[j].y, inv, scale);
                float a2 = bfp_apply(v[j].z, inv, scale);
                float a3 = bfp_apply(v[j].w, inv, scale);
                __nv_bfloat162 p0 = __floats2bfloat162_rn(a0, a1);  // exact
                __nv_bfloat162 p1 = __floats2bfloat162_rn(a2, a3);
                qg[j * 2]     = *(uint32_t*)&p0;
                qg[j * 2 + 1] = *(uint32_t*)&p1;
            }
        } else {
            #pragma unroll
            for (int j = 0; j < 18; ++j) qg[j] = 0u;
        }
        __syncthreads();

        const uint2* q2 = (const uint2*)s;
        uint2* o2 = (uint2*)g_xq_nchw;
        #pragma unroll
        for (int k = 0; k < 9; ++k) {
            long long go = b4 + tid + k * 256;
            if (go < NE_X4) o2[go] = q2[tid + k * 256];
        }
    } else {
        // ---------- w part: warp-per-group ----------
        int g = (blockIdx.x - NBX) * 8 + (tid >> 5);
        if (g >= NG_W) return;
        int lane = tid & 31;
        int base = g * 36;
        int i1 = base + lane;
        int i2 = base + 32 + lane;
        float v1 = w[i1];
        float v2 = (lane < 4) ? w[i2] : 0.0f;
        float m = fmaxf(fabsf(v1), fabsf(v2));
        #pragma unroll
        for (int o = 16; o > 0; o >>= 1)
            m = fmaxf(m, __shfl_xor_sync(0xffffffffu, m, o));
        if (m > 0.0f) {
            int e;
            frexpf(m, &e);
            float scale = ldexpf(1.0f, e - 8);
            float inv   = ldexpf(1.0f, 8 - e);
            v1 = bfp_apply(v1, inv, scale);
            v2 = bfp_apply(v2, inv, scale);
        } else { v1 = 0.0f; v2 = 0.0f; }
        store_w(i1, v1);
        if (lane < 4) store_w(i2, v2);
    }
}

// ---------------- transpose xq: NCHW -> NHWC, 2 images per block ------
__global__ void __launch_bounds__(256)
transpose_x_kernel() {
    __shared__ uint32_t t[2][32][33];
    const int tid  = threadIdx.x;
    const int hwp0 = blockIdx.x * 32;
    const int c0   = blockIdx.y * 32;
    const int n0   = blockIdx.z * 2;

    #pragma unroll
    for (int ni = 0; ni < 2; ++ni) {
        const uint32_t* src = (const uint32_t*)(g_xq_nchw + (long long)(n0 + ni) * CHW);
        #pragma unroll
        for (int p = 0; p < 4; ++p) {
            int cl  = p * 8 + (tid >> 5);
            int hwl = tid & 31;
            t[ni][cl][hwl] = src[(long long)(c0 + cl) * (HW / 2) + hwp0 + hwl];
        }
    }
    __syncthreads();

    const int cp = tid & 15;
    #pragma unroll
    for (int ni = 0; ni < 2; ++ni) {
        uint32_t* dst = (uint32_t*)(g_xq + (long long)(n0 + ni) * CHW);
        #pragma unroll
        for (int qq = 0; qq < 4; ++qq) {
            int hwl = (tid >> 4) + qq * 16;
            uint32_t u0 = t[ni][2 * cp][hwl >> 1];
            uint32_t u1 = t[ni][2 * cp + 1][hwl >> 1];
            uint32_t d = (hwl & 1) ? __byte_perm(u0, u1, 0x7632)
                                   : __byte_perm(u0, u1, 0x5410);
            dst[(long long)(hwp0 * 2 + hwl) * (C_ / 2) + (c0 >> 1) + cp] = d;
        }
    }
}

// ---------------- MMA / async-copy primitives ----------------
__device__ __forceinline__ void mma16816(float* d, const uint32_t* a, const uint32_t* b) {
    asm volatile(
        "mma.sync.aligned.m16n8k16.row.col.f32.bf16.bf16.f32 "
        "{%0,%1,%2,%3}, {%4,%5,%6,%7}, {%8,%9}, {%0,%1,%2,%3};\n"
        : "+f"(d[0]), "+f"(d[1]), "+f"(d[2]), "+f"(d[3])
        : "r"(a[0]), "r"(a[1]), "r"(a[2]), "r"(a[3]),
          "r"(b[0]), "r"(b[1]));
}

__device__ __forceinline__ void ldsm_x4(uint32_t* r, uint32_t addr) {
    asm volatile("ldmatrix.sync.aligned.m8n8.x4.shared.b16 {%0,%1,%2,%3}, [%4];\n"
                 : "=r"(r[0]), "=r"(r[1]), "=r"(r[2]), "=r"(r[3]) : "r"(addr));
}

__device__ __forceinline__ void cp_async16(uint32_t saddr, const void* g, int src_sz) {
    asm volatile("cp.async.cg.shared.global [%0], [%1], 16, %2;\n"
                 :: "r"(saddr), "l"(g), "r"(src_sz));
}
__device__ __forceinline__ void cp_commit() { asm volatile("cp.async.commit_group;\n"); }
__device__ __forceinline__ void cp_wait1()  { asm volatile("cp.async.wait_group 1;\n"); }

// ---------------- conv: 128M x 64N tile, BK=64, 3-stage, 3 CTAs/SM ----------
static constexpr int TILE_A    = 128 * 64 * 2;    // 16 KB
static constexpr int TILE_BB   = 64 * 64 * 2;     // 8 KB
static constexpr int STAGE_B   = TILE_A + TILE_BB; // 24 KB
static constexpr int CONV_SMEM = 3 * STAGE_B + 1024;   // 74752

__global__ void __launch_bounds__(256, 3)
conv_kernel(const float* __restrict__ bias, float* __restrict__ out) {
    extern __shared__ char dsm_raw[];
    __shared__ int s_n[128], s_pix[128];

    const int tid = threadIdx.x;
    const int m0  = blockIdx.y * 128;
    const int bn  = blockIdx.x;              // 0..3 (64-wide N tiles)

    const uint32_t dsm_u =
        ((uint32_t)__cvta_generic_to_shared(dsm_raw) + 1023u) & ~1023u;

    if (tid < 128) {
        int m  = m0 + tid;
        int nn = m / HW;
        s_n[tid]   = nn;
        s_pix[tid] = m - nn * HW;
    }

    // ---- loader metadata ----
    const int lc = tid & 7;
    const int lr = tid >> 3;                  // 0..31
    const uint32_t dst_off = (uint32_t)(lr * 128 + (lc ^ (lr & 7)) * 16);
    int am[4], ap[4], aq[4];
    #pragma unroll
    for (int p = 0; p < 4; ++p) {
        int m  = m0 + lr + 32 * p;
        int nn = m / HW;
        int rem = m - nn * HW;
        int hh = rem / W_;
        ap[p] = hh;
        aq[p] = rem - hh * W_;
        am[p] = m;
    }

    // ---- MMA fragment addressing: warp tile 32M x 32N ----
    const int lane = tid & 31, warp = tid >> 5;
    const int wm = warp & 3;                  // 4 warps along M
    const int wn = warp >> 2;                 // 2 warps along N
    const int l7 = lane & 7;
    uint32_t a_row_b[2], b_row_b[2];
    #pragma unroll
    for (int i = 0; i < 2; ++i)
        a_row_b[i] = (uint32_t)((wm * 32 + i * 16 + (lane & 15)) * 128);
    #pragma unroll
    for (int jj = 0; jj < 2; ++jj)
        b_row_b[jj] = (uint32_t)((wn * 32 + jj * 16 + l7 + ((lane >> 4) << 3)) * 128);
    const int a_chi = lane >> 4;
    const int b_chi = (lane >> 3) & 1;

    float acc[2][4][4];
    #pragma unroll
    for (int i = 0; i < 2; ++i)
        #pragma unroll
        for (int j = 0; j < 4; ++j)
            #pragma unroll
            for (int k = 0; k < 4; ++k) acc[i][j][k] = 0.0f;

    auto load_stage = [&](int kt, int buf) {
        int cb = kt / 9;
        int rs = kt - cb * 9;
        int r  = rs / 3;
        int s  = rs - r * 3;
        int doff  = (r - 1) * 56 + (s - 1);
        int cbase = cb * 64;
        uint32_t adst = dsm_u + (uint32_t)buf * STAGE_B + dst_off;
        uint32_t bdst = adst + (uint32_t)TILE_A;
        #pragma unroll
        for (int p = 0; p < 4; ++p) {
            int h = ap[p] + r - 1;
            int w = aq[p] + s - 1;
            bool ok = ((unsigned)h < 56u) && ((unsigned)w < 56u);
            long long off = ok ? ((long long)(am[p] + doff) * C_ + cbase + lc * 8) : 0ll;
            cp_async16(adst + (uint32_t)(p * 32 * 128), g_xq + off, ok ? 16 : 0);
        }
        #pragma unroll
        for (int p = 0; p < 2; ++p) {
            int kout = lr + 32 * p;           // 0..63
            cp_async16(bdst + (uint32_t)(p * 32 * 128),
                       g_wt + ((rs * K_ + bn * 64 + kout) * C_ + cbase + lc * 8), 16);
        }
    };

    auto do_kku = [&](uint32_t Ab, uint32_t Bb, int kku) {
        const int cu = kku * 2;
        uint32_t a[2][4], b[2][4];
        #pragma unroll
        for (int i = 0; i < 2; ++i)
            ldsm_x4(a[i], Ab + a_row_b[i] + (uint32_t)(((cu + a_chi) ^ l7) * 16));
        #pragma unroll
        for (int jj = 0; jj < 2; ++jj)
            ldsm_x4(b[jj], Bb + b_row_b[jj] + (uint32_t)(((cu + b_chi) ^ l7) * 16));
        #pragma unroll
        for (int i = 0; i < 2; ++i)
            #pragma unroll
            for (int j = 0; j < 4; ++j)
                mma16816(acc[i][j], a[i], &b[j >> 1][(j & 1) * 2]);
    };

    // proven ordering: wait -> barrier -> compute, loads between kku0 and kku1
    auto kstep = [&](int kt, int buf, int bufl) {
        cp_wait1();
        __syncthreads();

        const uint32_t Ab = dsm_u + (uint32_t)buf * STAGE_B;
        const uint32_t Bb = Ab + (uint32_t)TILE_A;

        do_kku(Ab, Bb, 0);
        if (kt + 2 < 36) load_stage(kt + 2, bufl);
        cp_commit();
        do_kku(Ab, Bb, 1);
        do_kku(Ab, Bb, 2);
        do_kku(Ab, Bb, 3);
    };

    __syncthreads();
    load_stage(0, 0); cp_commit();
    load_stage(1, 1); cp_commit();

    for (int kt = 0; kt < 36; kt += 3) {
        kstep(kt + 0, 0, 2);
        kstep(kt + 1, 1, 0);
        kstep(kt + 2, 2, 1);
    }

    // ---- epilogue ----
    const int gi = lane >> 2, ti = lane & 3;
    #pragma unroll
    for (int i = 0; i < 2; ++i) {
        int rl0 = wm * 32 + i * 16 + gi;
        int rl1 = rl0 + 8;
        int o0 = s_n[rl0] * CHW + s_pix[rl0];
        int o1 = s_n[rl1] * CHW + s_pix[rl1];
        #pragma unroll
        for (int j = 0; j < 4; ++j) {
            int kout = bn * 64 + wn * 32 + j * 8 + ti * 2;
            float b0 = bias[kout];
            float b1 = bias[kout + 1];
            out[o0 + kout * HW]       = acc[i][j][0] + b0;
            out[o0 + (kout + 1) * HW] = acc[i][j][1] + b1;
            out[o1 + kout * HW]       = acc[i][j][2] + b0;
            out[o1 + (kout + 1) * HW] = acc[i][j][3] + b1;
        }
    }
}

// ---------------- launch ----------------
extern "C" void kernel_launch(void* const* d_in, const int* in_sizes, int n_in,
                              void* d_out, int out_size) {
    const float* x    = (const float*)d_in[0];
    const float* w    = (const float*)d_in[1];
    const float* bias = (const float*)d_in[2];
    float* out = (float*)d_out;

    cudaFuncSetAttribute(conv_kernel, cudaFuncAttributeMaxDynamicSharedMemorySize, CONV_SMEM);

    quant_kernel<<<NBX + NBW, 256>>>(x, w);
    {
        dim3 g(49, 8, 8);
        transpose_x_kernel<<<g, 256>>>();
    }
    {
        dim3 g(4, MGEMM / 128);
        conv_kernel<<<g, 256, CONV_SMEM>>>(bias, out);
    }
}

// round 14
// speedup vs baseline: 1.0608x; 1.0608x over previous
#include <cuda_runtime.h>
#include <cuda_bf16.h>
#include <cstdint>

// ---------------- problem constants ----------------
static constexpr int N_  = 16;
static constexpr int C_  = 256;
static constexpr int H_  = 56;
static constexpr int W_  = 56;
static constexpr int K_  = 256;
static constexpr int HW  = H_ * W_;          // 3136
static constexpr int CHW = C_ * HW;          // 802816
static constexpr long long NE_X = (long long)N_ * CHW;   // 12,845,056
static constexpr int NE_W = K_ * C_ * 9;     // 589,824
static constexpr int NG_W = NE_W / 36;       // 16,384
static constexpr int MGEMM = N_ * HW;        // 50,176 = 392*128
static constexpr int NTILES = (MGEMM / 128) * 2;          // 784
static constexpr int CONV_GRID = 296;                     // 148 SMs * 2 CTAs

// ---------------- device scratch ----------------
__device__ __nv_bfloat16 g_xq_nchw[12845056];
__device__ __nv_bfloat16 g_xq[12845056];        // NHWC
__device__ __nv_bfloat16 g_wt[9 * 256 * 256];   // [rs][kout][c]
__device__ unsigned int  g_tile_ctr;            // persistent-conv work counter

// ---------------- BFP quantization ----------------
__device__ __forceinline__ float bfp_apply(float v, float inv, float scale) {
    float r = rintf(v * inv);                 // round-half-even == jnp.round
    r = fminf(fmaxf(r, -128.0f), 127.0f);
    return r * scale;
}

// ---------------- fused quantize: x blocks + w blocks in one launch ----------
static constexpr int QX_GROUPS = 256;
static constexpr int QX_ELEMS  = QX_GROUPS * 36;          // 9216
static constexpr long long NE_X4 = NE_X / 4;              // float4 count (exact)
static constexpr int NBX = (int)((NE_X + QX_ELEMS - 1) / QX_ELEMS);   // 1394
static constexpr int NBW = NG_W / 8;                      // 2048

__device__ __forceinline__ void store_w(int f, float q) {
    int kout = f / 2304;
    int rem  = f - kout * 2304;
    int c    = rem / 9;
    int rs   = rem - c * 9;
    g_wt[(rs * K_ + kout) * C_ + c] = __float2bfloat16(q);
}

__global__ void __launch_bounds__(256)
quant_kernel(const float* __restrict__ x, const float* __restrict__ w) {
    const int tid = threadIdx.x;
    if (blockIdx.x == 0 && tid == 0) g_tile_ctr = CONV_GRID;   // reset each launch
    if (blockIdx.x < (unsigned)NBX) {
        __shared__ float s[QX_ELEMS];                     // 36 KB
        const long long b4 = (long long)blockIdx.x * (QX_ELEMS / 4);

        const float4* x4 = (const float4*)x;
        float4* s4 = (float4*)s;
        #pragma unroll
        for (int k = 0; k < 9; ++k) {
            long long f = b4 + tid + k * 256;
            float4 v = (f < NE_X4) ? x4[f] : make_float4(0.f, 0.f, 0.f, 0.f);
            s4[tid + k * 256] = v;
        }
        __syncthreads();

        float4 v[9];
        const float4* sg4 = (const float4*)s + tid * 9;
        #pragma unroll
        for (int j = 0; j < 9; ++j) v[j] = sg4[j];

        float m = 0.0f;
        #pragma unroll
        for (int j = 0; j < 9; ++j)
            m = fmaxf(m, fmaxf(fmaxf(fabsf(v[j].x), fabsf(v[j].y)),
                               fmaxf(fabsf(v[j].z), fabsf(v[j].w))));
        float scale = 0.0f, inv = 0.0f;
        if (m > 0.0f) {
            int e;
            frexpf(m, &e);
            scale = ldexpf(1.0f, e - 8);
            inv   = ldexpf(1.0f, 8 - e);
        }
        __syncthreads();     // all reads done before in-place overwrite

        uint32_t* qg = (uint32_t*)s + tid * 18;
        if (m > 0.0f) {
            #pragma unroll
            for (int j = 0; j < 9; ++j) {
                float a0 = bfp_apply(v[j].x, inv, scale);
                float a1 = bfp_apply(v[j].y, inv, scale);
                float a2 = bfp_apply(v[j].z, inv, scale);
                float a3 = bfp_apply(v[j].w, inv, scale);
                __nv_bfloat162 p0 = __floats2bfloat162_rn(a0, a1);  // exact
                __nv_bfloat162 p1 = __floats2bfloat162_rn(a2, a3);
                qg[j * 2]     = *(uint32_t*)&p0;
                qg[j * 2 + 1] = *(uint32_t*)&p1;
            }
        } else {
            #pragma unroll
            for (int j = 0; j < 18; ++j) qg[j] = 0u;
        }
        __syncthreads();

        const uint2* q2 = (const uint2*)s;
        uint2* o2 = (uint2*)g_xq_nchw;
        #pragma unroll
        for (int k = 0; k < 9; ++k) {
            long long go = b4 + tid + k * 256;
            if (go < NE_X4) o2[go] = q2[tid + k * 256];
        }
    } else {
        // ---------- w part: warp-per-group ----------
        int g = (blockIdx.x - NBX) * 8 + (tid >> 5);
        if (g >= NG_W) return;
        int lane = tid & 31;
        int base = g * 36;
        int i1 = base + lane;
        int i2 = base + 32 + lane;
        float v1 = w[i1];
        float v2 = (lane < 4) ? w[i2] : 0.0f;
        float m = fmaxf(fabsf(v1), fabsf(v2));
        #pragma unroll
        for (int o = 16; o > 0; o >>= 1)
            m = fmaxf(m, __shfl_xor_sync(0xffffffffu, m, o));
        if (m > 0.0f) {
            int e;
            frexpf(m, &e);
            float scale = ldexpf(1.0f, e - 8);
            float inv   = ldexpf(1.0f, 8 - e);
            v1 = bfp_apply(v1, inv, scale);
            v2 = bfp_apply(v2, inv, scale);
        } else { v1 = 0.0f; v2 = 0.0f; }
        store_w(i1, v1);
        if (lane < 4) store_w(i2, v2);
    }
}

// ---------------- transpose xq: NCHW -> NHWC, 2 images per block ------
__global__ void __launch_bounds__(256)
transpose_x_kernel() {
    __shared__ uint32_t t[2][32][33];
    const int tid  = threadIdx.x;
    const int hwp0 = blockIdx.x * 32;
    const int c0   = blockIdx.y * 32;
    const int n0   = blockIdx.z * 2;

    #pragma unroll
    for (int ni = 0; ni < 2; ++ni) {
        const uint32_t* src = (const uint32_t*)(g_xq_nchw + (long long)(n0 + ni) * CHW);
        #pragma unroll
        for (int p = 0; p < 4; ++p) {
            int cl  = p * 8 + (tid >> 5);
            int hwl = tid & 31;
            t[ni][cl][hwl] = src[(long long)(c0 + cl) * (HW / 2) + hwp0 + hwl];
        }
    }
    __syncthreads();

    const int cp = tid & 15;
    #pragma unroll
    for (int ni = 0; ni < 2; ++ni) {
        uint32_t* dst = (uint32_t*)(g_xq + (long long)(n0 + ni) * CHW);
        #pragma unroll
        for (int qq = 0; qq < 4; ++qq) {
            int hwl = (tid >> 4) + qq * 16;
            uint32_t u0 = t[ni][2 * cp][hwl >> 1];
            uint32_t u1 = t[ni][2 * cp + 1][hwl >> 1];
            uint32_t d = (hwl & 1) ? __byte_perm(u0, u1, 0x7632)
                                   : __byte_perm(u0, u1, 0x5410);
            dst[(long long)(hwp0 * 2 + hwl) * (C_ / 2) + (c0 >> 1) + cp] = d;
        }
    }
}

// ---------------- MMA / async-copy primitives ----------------
__device__ __forceinline__ void mma16816(float* d, const uint32_t* a, const uint32_t* b) {
    asm volatile(
        "mma.sync.aligned.m16n8k16.row.col.f32.bf16.bf16.f32 "
        "{%0,%1,%2,%3}, {%4,%5,%6,%7}, {%8,%9}, {%0,%1,%2,%3};\n"
        : "+f"(d[0]), "+f"(d[1]), "+f"(d[2]), "+f"(d[3])
        : "r"(a[0]), "r"(a[1]), "r"(a[2]), "r"(a[3]),
          "r"(b[0]), "r"(b[1]));
}

__device__ __forceinline__ void ldsm_x4(uint32_t* r, uint32_t addr) {
    asm volatile("ldmatrix.sync.aligned.m8n8.x4.shared.b16 {%0,%1,%2,%3}, [%4];\n"
                 : "=r"(r[0]), "=r"(r[1]), "=r"(r[2]), "=r"(r[3]) : "r"(addr));
}

__device__ __forceinline__ void cp_async16(uint32_t saddr, const void* g, int src_sz) {
    asm volatile("cp.async.cg.shared.global [%0], [%1], 16, %2;\n"
                 :: "r"(saddr), "l"(g), "r"(src_sz));
}
__device__ __forceinline__ void cp_commit() { asm volatile("cp.async.commit_group;\n"); }
__device__ __forceinline__ void cp_wait1()  { asm volatile("cp.async.wait_group 1;\n"); }

// ---------------- conv: persistent CTAs, 128Mx128N tile, 3-stage (R12 core) ----
static constexpr int TILE_B    = 128 * 64 * 2;    // 16 KB per A or B tile (BK=64 bf16)
static constexpr int STAGE_B   = 2 * TILE_B;      // 32 KB
static constexpr int CONV_SMEM = 3 * STAGE_B + 1024;

__global__ void __launch_bounds__(256, 2)
conv_kernel(const float* __restrict__ bias, float* __restrict__ out) {
    extern __shared__ char dsm_raw[];
    __shared__ int s_n[128], s_pix[128];
    __shared__ int s_next;

    const int tid = threadIdx.x;
    const uint32_t dsm_u =
        ((uint32_t)__cvta_generic_to_shared(dsm_raw) + 1023u) & ~1023u;

    // ---- tile-invariant thread constants ----
    const int lc = tid & 7;
    const int lr = tid >> 3;
    const uint32_t dst_off = (uint32_t)(lr * 128 + (lc ^ (lr & 7)) * 16);
    const int lane = tid & 31, warp = tid >> 5;
    const int wm = warp & 1;
    const int wn = warp >> 1;
    const int l7 = lane & 7;
    uint32_t a_row_b[4], b_row_b[2];
    #pragma unroll
    for (int i = 0; i < 4; ++i)
        a_row_b[i] = (uint32_t)((wm * 64 + i * 16 + (lane & 15)) * 128);
    #pragma unroll
    for (int jj = 0; jj < 2; ++jj)
        b_row_b[jj] = (uint32_t)((wn * 32 + jj * 16 + l7 + ((lane >> 4) << 3)) * 128);
    const int a_chi = lane >> 4;
    const int b_chi = (lane >> 3) & 1;
    const int gi = lane >> 2, ti = lane & 3;

    int tile = blockIdx.x;
    while (tile < NTILES) {
        const int m0 = (tile >> 1) * 128;
        const int bn = tile & 1;

        if (tid < 128) {
            int m  = m0 + tid;
            int nn = m / HW;
            s_n[tid]   = nn;
            s_pix[tid] = m - nn * HW;
        }

        // ---- per-tile loader metadata ----
        int am[4], ap[4], aq[4];
        #pragma unroll
        for (int p = 0; p < 4; ++p) {
            int m  = m0 + lr + 32 * p;
            int nn = m / HW;
            int rem = m - nn * HW;
            int hh = rem / W_;
            ap[p] = hh;
            aq[p] = rem - hh * W_;
            am[p] = m;
        }

        float acc[4][4][4];
        #pragma unroll
        for (int i = 0; i < 4; ++i)
            #pragma unroll
            for (int j = 0; j < 4; ++j)
                #pragma unroll
                for (int k = 0; k < 4; ++k) acc[i][j][k] = 0.0f;

        auto load_stage = [&](int kt, int buf) {
            int cb = kt / 9;
            int rs = kt - cb * 9;
            int r  = rs / 3;
            int s  = rs - r * 3;
            int doff  = (r - 1) * 56 + (s - 1);
            int cbase = cb * 64;
            uint32_t adst = dsm_u + (uint32_t)buf * STAGE_B + dst_off;
            uint32_t bdst = adst + (uint32_t)TILE_B;
            #pragma unroll
            for (int p = 0; p < 4; ++p) {
                int h = ap[p] + r - 1;
                int w = aq[p] + s - 1;
                bool ok = ((unsigned)h < 56u) && ((unsigned)w < 56u);
                long long off = ok ? ((long long)(am[p] + doff) * C_ + cbase + lc * 8) : 0ll;
                cp_async16(adst + (uint32_t)(p * 32 * 128), g_xq + off, ok ? 16 : 0);
            }
            #pragma unroll
            for (int p = 0; p < 4; ++p) {
                int kout = lr + 32 * p;
                cp_async16(bdst + (uint32_t)(p * 32 * 128),
                           g_wt + ((rs * K_ + bn * 128 + kout) * C_ + cbase + lc * 8), 16);
            }
        };

        auto do_kku = [&](uint32_t Ab, uint32_t Bb, int kku) {
            const int cu = kku * 2;
            uint32_t a[4][4], b[2][4];
            #pragma unroll
            for (int i = 0; i < 4; ++i)
                ldsm_x4(a[i], Ab + a_row_b[i] + (uint32_t)(((cu + a_chi) ^ l7) * 16));
            #pragma unroll
            for (int jj = 0; jj < 2; ++jj)
                ldsm_x4(b[jj], Bb + b_row_b[jj] + (uint32_t)(((cu + b_chi) ^ l7) * 16));
            #pragma unroll
            for (int i = 0; i < 4; ++i)
                #pragma unroll
                for (int j = 0; j < 4; ++j)
                    mma16816(acc[i][j], a[i], &b[j >> 1][(j & 1) * 2]);
        };

        auto kstep = [&](int kt, int buf, int bufl) {
            cp_wait1();
            __syncthreads();

            const uint32_t Ab = dsm_u + (uint32_t)buf * STAGE_B;
            const uint32_t Bb = Ab + (uint32_t)TILE_B;

            do_kku(Ab, Bb, 0);
            if (kt + 2 < 36) load_stage(kt + 2, bufl);
            cp_commit();
            do_kku(Ab, Bb, 1);
            do_kku(Ab, Bb, 2);
            do_kku(Ab, Bb, 3);
        };

        __syncthreads();              // close previous tile's smem reads
        load_stage(0, 0); cp_commit();
        load_stage(1, 1); cp_commit();

        for (int kt = 0; kt < 36; kt += 3) {
            kstep(kt + 0, 0, 2);
            kstep(kt + 1, 1, 0);
            kstep(kt + 2, 2, 1);
        }

        // ---- epilogue (direct stores) ----
        #pragma unroll
        for (int i = 0; i < 4; ++i) {
            int rl0 = wm * 64 + i * 16 + gi;
            int rl1 = rl0 + 8;
            int o0 = s_n[rl0] * CHW + s_pix[rl0];
            int o1 = s_n[rl1] * CHW + s_pix[rl1];
            #pragma unroll
            for (int j = 0; j < 4; ++j) {
                int kout = bn * 128 + wn * 32 + j * 8 + ti * 2;
                float b0 = bias[kout];
                float b1 = bias[kout + 1];
                out[o0 + kout * HW]       = acc[i][j][0] + b0;
                out[o0 + (kout + 1) * HW] = acc[i][j][1] + b1;
                out[o1 + kout * HW]       = acc[i][j][2] + b0;
                out[o1 + (kout + 1) * HW] = acc[i][j][3] + b1;
            }
        }

        // ---- fetch next tile (dynamic schedule) ----
        if (tid == 0) s_next = (int)atomicAdd(&g_tile_ctr, 1u);
        __syncthreads();              // publish s_next; also guards s_n rewrite
        tile = s_next;
    }
}

// ---------------- launch ----------------
extern "C" void kernel_launch(void* const* d_in, const int* in_sizes, int n_in,
                              void* d_out, int out_size) {
    const float* x    = (const float*)d_in[0];
    const float* w    = (const float*)d_in[1];
    const float* bias = (const float*)d_in[2];
    float* out = (float*)d_out;

    cudaFuncSetAttribute(conv_kernel, cudaFuncAttributeMaxDynamicSharedMemorySize, CONV_SMEM);

    quant_kernel<<<NBX + NBW, 256>>>(x, w);
    {
        dim3 g(49, 8, 8);
        transpose_x_kernel<<<g, 256>>>();
    }
    conv_kernel<<<CONV_GRID, 256, CONV_SMEM>>>(bias, out);
}